// round 9
// baseline (speedup 1.0000x reference)
#include <cuda_runtime.h>
#include <math.h>
#include <stdint.h>

// ===========================================================================
// img_attention via warp-level TF32 mma.sync (compute_103-safe)
//   c_img = softmax(v . tanh(Wh g* + Ws s + Wc cov)) @ g*
//   g*    = X @ (W_g @ W_gs) + (b_g @ W_gs + b_gs)      [algebraic fold]
// GEMMs: D[m,n] = sum_k A[m,k] * Bt[n,k]  (both K-major)
// R8: RNA rounding moved onto ldmatrix fragments (templated per-operand) —
//     X / W_g gmem rounding passes eliminated. bias_init folded into prep.
// ===========================================================================

#define B_   128
#define N_   49
#define G_   4096
#define H_   1024
#define A_   1024
#define BN_  (B_ * N_)   // 6272

__device__ float g_WcombT[H_ * G_];     // [1024,4096] (rounded)
__device__ float g_biascomb[H_];
__device__ float g_gstar[BN_ * H_];     // [6272,1024] (rounded)
__device__ float g_WgsT[H_ * G_];       // W_gs^T rounded [1024,4096]
__device__ float g_WhT[A_ * H_];        // rounded
__device__ float g_WsT[A_ * H_];        // rounded
__device__ float g_str[B_ * H_];        // s_t rounded
__device__ float g_sproj[B_ * A_];
__device__ float g_scores[BN_];

// ---------------------------------------------------------------------------
__device__ __forceinline__ uint32_t smem_u32(const void* p) {
    uint32_t a;
    asm("{ .reg .u64 t; cvta.to.shared.u64 t, %1; cvt.u32.u64 %0, t; }"
        : "=r"(a) : "l"(p));
    return a;
}
__device__ __forceinline__ float to_tf32(float x) {
    uint32_t u;
    asm("cvt.rna.tf32.f32 %0, %1;" : "=r"(u) : "f"(x));
    return __uint_as_float(u);
}
__device__ __forceinline__ uint32_t to_tf32_u(uint32_t x) {
    uint32_t u;
    asm("cvt.rna.tf32.f32 %0, %1;" : "=r"(u) : "f"(__uint_as_float(x)));
    return u;
}
__device__ __forceinline__ float tanh_approx(float x) {
    float y;
    asm("tanh.approx.f32 %0, %1;" : "=f"(y) : "f"(x));
    return y;
}
__device__ __forceinline__ void ldsm4(uint32_t* r, uint32_t addr) {
    asm volatile("ldmatrix.sync.aligned.m8n8.x4.shared.b16 {%0,%1,%2,%3}, [%4];"
                 : "=r"(r[0]), "=r"(r[1]), "=r"(r[2]), "=r"(r[3]) : "r"(addr));
}
__device__ __forceinline__ void mma_tf32(float* d, const uint32_t* a,
                                         const uint32_t* b) {
    asm volatile(
        "mma.sync.aligned.m16n8k8.row.col.f32.tf32.tf32.f32 "
        "{%0,%1,%2,%3}, {%4,%5,%6,%7}, {%8,%9}, {%0,%1,%2,%3};"
        : "+f"(d[0]), "+f"(d[1]), "+f"(d[2]), "+f"(d[3])
        : "r"(a[0]), "r"(a[1]), "r"(a[2]), "r"(a[3]), "r"(b[0]), "r"(b[1]));
}
#define CPA(dst, src) \
    asm volatile("cp.async.cg.shared.global [%0], [%1], 16;" \
                 :: "r"(dst), "l"(src) : "memory")
#define CPCOMMIT() asm volatile("cp.async.commit_group;" ::: "memory")
#define CPWAIT1()  asm volatile("cp.async.wait_group 1;" ::: "memory")
#define CPWAIT0()  asm volatile("cp.async.wait_group 0;" ::: "memory")

// ---------------------------------------------------------------------------
// GEMM machinery: 128x128 block, BK=32, 128 threads, 2x2 warps of 64x64.
// 3-stage cp.async ring: 3 x (16KB A + 16KB B) = 96KB.
// CVTA/CVTB: apply cvt.rna.tf32 to A/B fragments post-ldmatrix (compile-time).
// ---------------------------------------------------------------------------
#define STAGE_B 32768
#define TCSM (3 * STAGE_B)

#define GEMM_PROLOG()                                                         \
    extern __shared__ char smem[];                                            \
    const uint32_t sb = smem_u32(smem);                                       \
    const int tid = threadIdx.x;                                              \
    const int lane = tid & 31;                                                \
    const int wid = tid >> 5;                                                 \
    const int wr = wid >> 1;   /* 0..1 */                                     \
    const int wc = wid & 1;    /* 0..1 */                                     \
    const int srow = tid >> 3, sc4 = tid & 7;                                 \
    const uint32_t soff0 = (uint32_t)srow * 128 + ((sc4 ^ (srow & 7)) << 4);  \
    const int aRow = wr * 64 + ((lane >> 3) & 1) * 8 + (lane & 7);            \
    const int cbA = lane >> 4;                                                \
    const uint32_t aBase = (uint32_t)aRow * 128;                              \
    const int rmA = aRow & 7;                                                 \
    const int bRow = wc * 64 + (lane >> 4) * 8 + (lane & 7);                  \
    const int cbB = (lane >> 3) & 1;                                          \
    const uint32_t bBase = (uint32_t)bRow * 128;                              \
    const int rmB = bRow & 7;                                                 \
    float acc[4][8][4];                                                       \
    _Pragma("unroll") for (int i = 0; i < 4; i++)                             \
        _Pragma("unroll") for (int j = 0; j < 8; j++)                         \
            _Pragma("unroll") for (int q = 0; q < 4; q++) acc[i][j][q] = 0.f;

#define ISSUE_STAGE(sbase, k0) {                                              \
    _Pragma("unroll") for (int j = 0; j < 8; j++) {                           \
        CPA((sbase) + soff0 + j * 2048,         pA0 + (k0) + j * strideJ);    \
        CPA((sbase) + 16384 + soff0 + j * 2048, pB0 + (k0) + j * strideJ);    \
    }                                                                         \
    CPCOMMIT(); }

#define COMPUTE_CHUNK(As, Bs, CA, CB) {                                       \
    _Pragma("unroll") for (int kc = 0; kc < 4; kc++) {                        \
        uint32_t afr[4][4], bfr[8][2];                                        \
        _Pragma("unroll") for (int fm = 0; fm < 4; fm++) {                    \
            ldsm4(afr[fm],                                                    \
                  (As) + fm * 2048 + aBase + ((((kc * 2) + cbA) ^ rmA) << 4));\
            if (CA) {                                                         \
                _Pragma("unroll") for (int q = 0; q < 4; q++)                 \
                    afr[fm][q] = to_tf32_u(afr[fm][q]);                       \
            }                                                                 \
        }                                                                     \
        _Pragma("unroll") for (int p = 0; p < 4; p++) {                       \
            uint32_t t4[4];                                                   \
            ldsm4(t4,                                                         \
                  (Bs) + p * 2048 + bBase + ((((kc * 2) + cbB) ^ rmB) << 4)); \
            if (CB) {                                                         \
                _Pragma("unroll") for (int q = 0; q < 4; q++)                 \
                    t4[q] = to_tf32_u(t4[q]);                                 \
            }                                                                 \
            bfr[2*p][0]   = t4[0]; bfr[2*p][1]   = t4[1];                     \
            bfr[2*p+1][0] = t4[2]; bfr[2*p+1][1] = t4[3];                     \
        }                                                                     \
        _Pragma("unroll") for (int fm = 0; fm < 4; fm++)                      \
            _Pragma("unroll") for (int fn = 0; fn < 8; fn++)                  \
                mma_tf32(acc[fm][fn], afr[fm], bfr[fn]);                      \
    } }

// 3-stage pipeline; requires nch >= 2.
#define MAINLOOP(nch, CA, CB)                                                 \
    ISSUE_STAGE(sb, 0);                                                       \
    ISSUE_STAGE(sb + STAGE_B, 32);                                            \
    { int cs = 0, is = 2;                                                     \
    for (int c = 0; c < (nch); c++) {                                         \
        if (c == (nch) - 1) { CPWAIT0(); } else { CPWAIT1(); }                \
        __syncthreads();                                                      \
        if (c + 2 < (nch)) {                                                  \
            ISSUE_STAGE(sb + is * STAGE_B, (c + 2) * 32);                     \
            is = (is == 2) ? 0 : is + 1;                                      \
        }                                                                     \
        COMPUTE_CHUNK(sb + cs * STAGE_B, sb + cs * STAGE_B + 16384, CA, CB);  \
        cs = (cs == 2) ? 0 : cs + 1;                                          \
    } }

// ---------------------------------------------------------------------------
// Generic GEMM: D = A @ Bt^T (+ bias), optional TF32-rounded store.
// CVTA/CVTB: round raw fp32 operand fragments (for unrounded gmem inputs).
// ---------------------------------------------------------------------------
template <int CVTA, int CVTB>
__global__ __launch_bounds__(128, 2)
void mma_gemm(const float* __restrict__ A, const float* __restrict__ Bt,
              const float* __restrict__ bias, float* __restrict__ C,
              int M, int Nn, int K, int roundC)
{
    const int bm = blockIdx.y * 128;
    const int bn = blockIdx.x * 128;
    GEMM_PROLOG();
    const float* pA0 = A  + (size_t)(bm + srow) * K + sc4 * 4;
    const float* pB0 = Bt + (size_t)(bn + srow) * K + sc4 * 4;
    const size_t strideJ = (size_t)16 * K;
    const int nch = K >> 5;
    MAINLOOP(nch, CVTA, CVTB);

    const int gid = lane >> 2, tig = lane & 3;
    #pragma unroll
    for (int fm = 0; fm < 4; fm++) {
        const int row = bm + wr * 64 + fm * 16 + gid;
        #pragma unroll
        for (int fn = 0; fn < 8; fn++) {
            const int col = bn + wc * 64 + fn * 8 + tig * 2;
            float b0 = 0.f, b1 = 0.f;
            if (bias != nullptr) { b0 = bias[col]; b1 = bias[col + 1]; }
            float2 v01, v23;
            v01.x = acc[fm][fn][0] + b0; v01.y = acc[fm][fn][1] + b1;
            v23.x = acc[fm][fn][2] + b0; v23.y = acc[fm][fn][3] + b1;
            if (roundC) {
                v01.x = to_tf32(v01.x); v01.y = to_tf32(v01.y);
                v23.x = to_tf32(v23.x); v23.y = to_tf32(v23.y);
            }
            *(float2*)(C + (size_t)row * Nn + col) = v01;
            *(float2*)(C + (size_t)(row + 8) * Nn + col) = v23;
        }
    }
}

// ---------------------------------------------------------------------------
// Split-K GEMM for skinny M=128: C += A @ Bt^T over K slice (atomics).
// ---------------------------------------------------------------------------
__global__ __launch_bounds__(128, 2)
void mma_gemm_splitk(const float* __restrict__ A, const float* __restrict__ Bt,
                     float* __restrict__ C, int M, int Nn, int K, int klen)
{
    const int bm = blockIdx.y * 128;
    const int bn = blockIdx.x * 128;
    const int kbase = blockIdx.z * klen;
    GEMM_PROLOG();
    const float* pA0 = A  + (size_t)(bm + srow) * K + kbase + sc4 * 4;
    const float* pB0 = Bt + (size_t)(bn + srow) * K + kbase + sc4 * 4;
    const size_t strideJ = (size_t)16 * K;
    const int nch = klen >> 5;
    MAINLOOP(nch, 0, 0);

    const int gid = lane >> 2, tig = lane & 3;
    #pragma unroll
    for (int fm = 0; fm < 4; fm++) {
        const int row = bm + wr * 64 + fm * 16 + gid;
        #pragma unroll
        for (int fn = 0; fn < 8; fn++) {
            const int col = bn + wc * 64 + fn * 8 + tig * 2;
            atomicAdd(C + (size_t)row * Nn + col,       acc[fm][fn][0]);
            atomicAdd(C + (size_t)row * Nn + col + 1,   acc[fm][fn][1]);
            atomicAdd(C + (size_t)(row+8) * Nn + col,   acc[fm][fn][2]);
            atomicAdd(C + (size_t)(row+8) * Nn + col+1, acc[fm][fn][3]);
        }
    }
}

// ---------------------------------------------------------------------------
// Fused e_pre GEMM + scores epilogue. acc = gstar @ WhT^T (K=1024), then
// scores[row] += sum_col v[col]*tanh(acc + sproj[b,col] + cov[row]*Wc[col])
// ---------------------------------------------------------------------------
__global__ __launch_bounds__(128, 2)
void epre_scores_gemm(const float* __restrict__ A, const float* __restrict__ Bt,
                      const float* __restrict__ sproj,
                      const float* __restrict__ cov,
                      const float* __restrict__ Wc,
                      const float* __restrict__ v,
                      float* __restrict__ scores)
{
    const int bm = blockIdx.y * 128;
    const int bn = blockIdx.x * 128;
    GEMM_PROLOG();
    const float* pA0 = A  + (size_t)(bm + srow) * H_ + sc4 * 4;
    const float* pB0 = Bt + (size_t)(bn + srow) * H_ + sc4 * 4;
    const size_t strideJ = (size_t)16 * H_;
    MAINLOOP(H_ / 32, 0, 0);

    const int gid = lane >> 2, tig = lane & 3;
    float vv[16], wcv[16];
    #pragma unroll
    for (int fn = 0; fn < 8; fn++) {
        const int col = bn + wc * 64 + fn * 8 + tig * 2;
        vv[2*fn]   = v[col];      vv[2*fn+1]  = v[col + 1];
        wcv[2*fn]  = Wc[col];     wcv[2*fn+1] = Wc[col + 1];
    }
    #pragma unroll
    for (int fm = 0; fm < 4; fm++) {
        const int r0 = bm + wr * 64 + fm * 16 + gid;
        const int r1 = r0 + 8;
        const int b0i = r0 / N_, b1i = r1 / N_;
        const float c0 = cov[r0], c1 = cov[r1];
        const float* sp0 = sproj + (size_t)b0i * A_;
        const float* sp1 = sproj + (size_t)b1i * A_;
        float p0 = 0.f, p1 = 0.f;
        #pragma unroll
        for (int fn = 0; fn < 8; fn++) {
            const int col = bn + wc * 64 + fn * 8 + tig * 2;
            p0 += vv[2*fn]   * tanh_approx(acc[fm][fn][0] + sp0[col]     + c0 * wcv[2*fn]);
            p0 += vv[2*fn+1] * tanh_approx(acc[fm][fn][1] + sp0[col + 1] + c0 * wcv[2*fn+1]);
            p1 += vv[2*fn]   * tanh_approx(acc[fm][fn][2] + sp1[col]     + c1 * wcv[2*fn]);
            p1 += vv[2*fn+1] * tanh_approx(acc[fm][fn][3] + sp1[col + 1] + c1 * wcv[2*fn+1]);
        }
        p0 += __shfl_xor_sync(0xffffffffu, p0, 1);
        p0 += __shfl_xor_sync(0xffffffffu, p0, 2);
        p1 += __shfl_xor_sync(0xffffffffu, p1, 1);
        p1 += __shfl_xor_sync(0xffffffffu, p1, 2);
        if (tig == 0) {
            atomicAdd(scores + r0, p0);
            atomicAdd(scores + r1, p1);
        }
    }
}

// ---------------------------------------------------------------------------
// Batched prologue: rounded transposes, zero-fills, s_t rounding, bias init.
// ---------------------------------------------------------------------------
#define PREP_T1 4096
#define PREP_T2 (PREP_T1 + 1024)
#define PREP_T3 (PREP_T2 + 1024)
#define PREP_ZS (PREP_T3 + 25)
#define PREP_ZP (PREP_ZS + 512)
#define PREP_RS (PREP_ZP + 128)        // s_t: 128*1024/4/256
#define PREP_BI (PREP_RS + 4)          // bias init: 1024/256
#define PREP_END PREP_BI

__device__ __forceinline__ void do_transpose32r(
    const float* __restrict__ in, float* __restrict__ out,
    int R, int C, int tx, int ty)
{
    __shared__ float t[32][33];
    const int c0 = tx * 32, r0 = ty * 32;
    const int x = threadIdx.x & 31, y = (threadIdx.x >> 5);
    #pragma unroll
    for (int j = 0; j < 32; j += 8)
        t[y + j][x] = in[(size_t)(r0 + y + j) * C + c0 + x];
    __syncthreads();
    #pragma unroll
    for (int j = 0; j < 32; j += 8)
        out[(size_t)(c0 + y + j) * R + r0 + x] = to_tf32(t[x][y + j]);
}

__global__ __launch_bounds__(256) void prep_kernel(
    const float* __restrict__ W_gs, float* __restrict__ WgsT,
    const float* __restrict__ W_h,  float* __restrict__ WhT,
    const float* __restrict__ W_s,  float* __restrict__ WsT,
    const float* __restrict__ s_t,  float* __restrict__ str,
    const float* __restrict__ b_gs, float* __restrict__ biascomb,
    float* __restrict__ scores, float* __restrict__ sproj)
{
    const int bid = blockIdx.x;
    if (bid < PREP_T1) {
        do_transpose32r(W_gs, WgsT, G_, H_, bid & 31, bid >> 5);
    } else if (bid < PREP_T2) {
        const int b = bid - PREP_T1;
        do_transpose32r(W_h, WhT, H_, A_, b & 31, b >> 5);
    } else if (bid < PREP_T3) {
        const int b = bid - PREP_T2;
        do_transpose32r(W_s, WsT, H_, A_, b & 31, b >> 5);
    } else if (bid < PREP_ZS) {
        const int i = (bid - PREP_T3) * 256 + threadIdx.x;
        if (i < BN_) scores[i] = 0.f;
    } else if (bid < PREP_ZP) {
        const int i = (bid - PREP_ZS) * 256 + threadIdx.x;
        sproj[i] = 0.f;
    } else if (bid < PREP_RS) {
        const int i = (bid - PREP_ZP) * 256 + threadIdx.x;
        float4 x = *(const float4*)(s_t + (size_t)i * 4);
        x.x = to_tf32(x.x); x.y = to_tf32(x.y);
        x.z = to_tf32(x.z); x.w = to_tf32(x.w);
        *(float4*)(str + (size_t)i * 4) = x;
    } else {
        const int h = (bid - PREP_RS) * 256 + threadIdx.x;
        biascomb[h] = b_gs[h];
    }
}

__global__ void bias_acc_kernel(const float* __restrict__ b_g,
                                const float* __restrict__ W_gs,
                                float* __restrict__ bias) {
    int h = blockIdx.x * blockDim.x + threadIdx.x;
    int k0 = blockIdx.y * 256;
    float acc = 0.f;
    #pragma unroll 4
    for (int k = k0; k < k0 + 256; k++)
        acc += b_g[k] * W_gs[(size_t)k * H_ + h];
    atomicAdd(&bias[h], acc);
}

// softmax over N=49 + context c[b,h] = sum_n alpha[n] * gstar[b,n,h]
__global__ __launch_bounds__(256) void context_kernel(
    const float* __restrict__ scores, const float* __restrict__ gstar,
    float* __restrict__ out)
{
    const int b = blockIdx.x;
    __shared__ float alpha[N_];
    const int tid = threadIdx.x;

    if (tid == 0) {
        float m = -1e30f;
        #pragma unroll
        for (int n = 0; n < N_; n++) m = fmaxf(m, scores[b * N_ + n]);
        float s = 0.f;
        #pragma unroll
        for (int n = 0; n < N_; n++) {
            float e = expf(scores[b * N_ + n] - m);
            alpha[n] = e;
            s += e;
        }
        float inv = 1.f / s;
        #pragma unroll
        for (int n = 0; n < N_; n++) alpha[n] *= inv;
    }
    __syncthreads();

    const float* gb = gstar + (size_t)b * N_ * H_;
    for (int h = tid; h < H_; h += 256) {
        float acc = 0.f;
        #pragma unroll
        for (int n = 0; n < N_; n++)
            acc += alpha[n] * gb[(size_t)n * H_ + h];
        out[(size_t)b * H_ + h] = acc;
    }
}

// ---------------------------------------------------------------------------
extern "C" void kernel_launch(void* const* d_in, const int* in_sizes, int n_in,
                              void* d_out, int out_size) {
    const float* X    = (const float*)d_in[0];   // [6272,4096]
    const float* s_t  = (const float*)d_in[1];   // [128,1024]
    const float* cov  = (const float*)d_in[2];   // [6272]
    const float* W_g  = (const float*)d_in[3];   // [4096,4096]
    const float* b_g  = (const float*)d_in[4];   // [4096]
    const float* W_gs = (const float*)d_in[5];   // [4096,1024]
    const float* b_gs = (const float*)d_in[6];   // [1024]
    const float* W_h  = (const float*)d_in[7];   // [1024,1024]
    const float* W_s  = (const float*)d_in[8];   // [1024,1024]
    const float* W_c  = (const float*)d_in[9];   // [1024]
    const float* v    = (const float*)d_in[10];  // [1024]
    float* out = (float*)d_out;                  // [128,1024]

    float *WcombT, *biascomb, *gstar, *WgsT, *WhT, *WsT;
    float *str, *sproj, *scores;
    cudaGetSymbolAddress((void**)&WcombT,   g_WcombT);
    cudaGetSymbolAddress((void**)&biascomb, g_biascomb);
    cudaGetSymbolAddress((void**)&gstar,    g_gstar);
    cudaGetSymbolAddress((void**)&WgsT,     g_WgsT);
    cudaGetSymbolAddress((void**)&WhT,      g_WhT);
    cudaGetSymbolAddress((void**)&WsT,      g_WsT);
    cudaGetSymbolAddress((void**)&str,      g_str);
    cudaGetSymbolAddress((void**)&sproj,    g_sproj);
    cudaGetSymbolAddress((void**)&scores,   g_scores);

    cudaFuncSetAttribute(mma_gemm<0, 1>,
                         cudaFuncAttributeMaxDynamicSharedMemorySize, TCSM);
    cudaFuncSetAttribute(mma_gemm<1, 0>,
                         cudaFuncAttributeMaxDynamicSharedMemorySize, TCSM);
    cudaFuncSetAttribute(mma_gemm_splitk,
                         cudaFuncAttributeMaxDynamicSharedMemorySize, TCSM);
    cudaFuncSetAttribute(epre_scores_gemm,
                         cudaFuncAttributeMaxDynamicSharedMemorySize, TCSM);

    // prologue: rounded transposes, zero-fills, s_t rounding, bias init
    prep_kernel<<<PREP_END, 256>>>(W_gs, WgsT, W_h, WhT, W_s, WsT,
                                   s_t, str, b_gs, biascomb, scores, sproj);
    bias_acc_kernel<<<dim3(H_ / 256, G_ / 256), 256>>>(b_g, W_gs, biascomb);

    // WcombT[h,g] = sum_k WgsT[h,k] * W_g[g,k]  (B=W_g raw -> cvt frags)
    mma_gemm<0, 1><<<dim3(G_ / 128, H_ / 128), 128, TCSM>>>(
        WgsT, W_g, nullptr, WcombT, H_, G_, G_, 1);

    // g_star[m,h] = sum_k X[m,k] * WcombT[h,k] + bias  (A=X raw -> cvt frags)
    mma_gemm<1, 0><<<dim3(H_ / 128, BN_ / 128), 128, TCSM>>>(
        X, WcombT, biascomb, gstar, BN_, H_, G_, 1);

    // s_proj[b,a] = sum_h str[b,h] * WsT[a,h]   (split-K x8, atomic)
    mma_gemm_splitk<<<dim3(A_ / 128, 1, 8), 128, TCSM>>>(
        str, WsT, sproj, B_, A_, H_, H_ / 8);

    // fused: e_pre + tanh + v-dot -> scores (epre never materialized)
    epre_scores_gemm<<<dim3(A_ / 128, BN_ / 128), 128, TCSM>>>(
        gstar, WhT, sproj, cov, W_c, v, scores);

    context_kernel<<<B_, 256>>>(scores, gstar, out);
}

// round 10
// speedup vs baseline: 1.0342x; 1.0342x over previous
#include <cuda_runtime.h>
#include <math.h>
#include <stdint.h>

// ===========================================================================
// img_attention via warp-level TF32 mma.sync (compute_103-safe)
//   c_img = softmax(v . tanh(Wh g* + Ws s + Wc cov)) @ g*
//   g*    = X @ (W_g @ W_gs) + (b_g @ W_gs + b_gs)      [algebraic fold]
// GEMMs: D[m,n] = sum_k A[m,k] * Bt[n,k]  (both K-major)
// R9: templated M-tile. gstar/epre use 64x128 tiles @ 3 CTAs/SM (12 warps)
//     to kill wave quantization (392-CTA grids were 1.32 waves over 296
//     slots -> 2 full waves). Wcomb keeps 128x128 (single wave already).
// ===========================================================================

#define B_   128
#define N_   49
#define G_   4096
#define H_   1024
#define A_   1024
#define BN_  (B_ * N_)   // 6272

__device__ float g_WcombT[H_ * G_];     // [1024,4096] (rounded)
__device__ float g_biascomb[H_];
__device__ float g_gstar[BN_ * H_];     // [6272,1024] (rounded)
__device__ float g_WgsT[H_ * G_];       // W_gs^T rounded [1024,4096]
__device__ float g_WhT[A_ * H_];        // rounded
__device__ float g_WsT[A_ * H_];        // rounded
__device__ float g_str[B_ * H_];        // s_t rounded
__device__ float g_sproj[B_ * A_];
__device__ float g_scores[BN_];

// ---------------------------------------------------------------------------
__device__ __forceinline__ uint32_t smem_u32(const void* p) {
    uint32_t a;
    asm("{ .reg .u64 t; cvta.to.shared.u64 t, %1; cvt.u32.u64 %0, t; }"
        : "=r"(a) : "l"(p));
    return a;
}
__device__ __forceinline__ float to_tf32(float x) {
    uint32_t u;
    asm("cvt.rna.tf32.f32 %0, %1;" : "=r"(u) : "f"(x));
    return __uint_as_float(u);
}
__device__ __forceinline__ uint32_t to_tf32_u(uint32_t x) {
    uint32_t u;
    asm("cvt.rna.tf32.f32 %0, %1;" : "=r"(u) : "f"(__uint_as_float(x)));
    return u;
}
__device__ __forceinline__ float tanh_approx(float x) {
    float y;
    asm("tanh.approx.f32 %0, %1;" : "=f"(y) : "f"(x));
    return y;
}
__device__ __forceinline__ void ldsm4(uint32_t* r, uint32_t addr) {
    asm volatile("ldmatrix.sync.aligned.m8n8.x4.shared.b16 {%0,%1,%2,%3}, [%4];"
                 : "=r"(r[0]), "=r"(r[1]), "=r"(r[2]), "=r"(r[3]) : "r"(addr));
}
__device__ __forceinline__ void mma_tf32(float* d, const uint32_t* a,
                                         const uint32_t* b) {
    asm volatile(
        "mma.sync.aligned.m16n8k8.row.col.f32.tf32.tf32.f32 "
        "{%0,%1,%2,%3}, {%4,%5,%6,%7}, {%8,%9}, {%0,%1,%2,%3};"
        : "+f"(d[0]), "+f"(d[1]), "+f"(d[2]), "+f"(d[3])
        : "r"(a[0]), "r"(a[1]), "r"(a[2]), "r"(a[3]), "r"(b[0]), "r"(b[1]));
}
#define CPA(dst, src) \
    asm volatile("cp.async.cg.shared.global [%0], [%1], 16;" \
                 :: "r"(dst), "l"(src) : "memory")
#define CPCOMMIT() asm volatile("cp.async.commit_group;" ::: "memory")
#define CPWAIT1()  asm volatile("cp.async.wait_group 1;" ::: "memory")
#define CPWAIT0()  asm volatile("cp.async.wait_group 0;" ::: "memory")

// ---------------------------------------------------------------------------
// Templated GEMM core. FM = A-fragments per warp (M-tile = FM*32).
//   FM=4: block 128x128, 2 CTAs/SM (96KB smem)
//   FM=2: block  64x128, 3 CTAs/SM (72KB smem)
// 2x2 warps; warp tile (FM*16)x64. BK=32. 3-stage cp.async ring.
// ---------------------------------------------------------------------------
template <int FM>
struct GemmDims {
    static const int ABYTES = FM * 32 * 128;      // A stage bytes
    static const int STAGE  = ABYTES + 16384;     // + B stage (128x32 f32)
    static const int SMEM   = 3 * STAGE;
    static const int OCC    = (FM == 2) ? 3 : 2;
};

#define GEMM_PROLOG(FM)                                                       \
    extern __shared__ char smem[];                                            \
    const uint32_t sb = smem_u32(smem);                                       \
    const int tid = threadIdx.x;                                              \
    const int lane = tid & 31;                                                \
    const int wid = tid >> 5;                                                 \
    const int wr = wid >> 1;   /* 0..1 */                                     \
    const int wc = wid & 1;    /* 0..1 */                                     \
    const int srow = tid >> 3, sc4 = tid & 7;                                 \
    const uint32_t soff0 = (uint32_t)srow * 128 + ((sc4 ^ (srow & 7)) << 4);  \
    const int aRow = wr * (FM * 16) + ((lane >> 3) & 1) * 8 + (lane & 7);     \
    const int cbA = lane >> 4;                                                \
    const uint32_t aBase = (uint32_t)aRow * 128;                              \
    const int rmA = aRow & 7;                                                 \
    const int bRow = wc * 64 + (lane >> 4) * 8 + (lane & 7);                  \
    const int cbB = (lane >> 3) & 1;                                          \
    const uint32_t bBase = (uint32_t)bRow * 128;                              \
    const int rmB = bRow & 7;                                                 \
    float acc[FM][8][4];                                                      \
    _Pragma("unroll") for (int i = 0; i < FM; i++)                            \
        _Pragma("unroll") for (int j = 0; j < 8; j++)                         \
            _Pragma("unroll") for (int q = 0; q < 4; q++) acc[i][j][q] = 0.f;

template <int FM, int CVTA, int CVTB>
__device__ __forceinline__ void gemm_core(
    const float* __restrict__ pA0, const float* __restrict__ pB0,
    size_t strideJ, int nch, uint32_t sb, uint32_t soff0,
    uint32_t aBase, int rmA, int cbA,
    uint32_t bBase, int rmB, int cbB,
    float (&acc)[FM][8][4])
{
    const int ABYTES = GemmDims<FM>::ABYTES;
    const int STAGE  = GemmDims<FM>::STAGE;
    const int JA = FM * 2;   // A float4-load iterations (8 or 4)

    auto issue = [&](uint32_t sbase, int k0) {
        #pragma unroll
        for (int j = 0; j < JA; j++)
            CPA(sbase + soff0 + j * 2048, pA0 + k0 + j * strideJ);
        #pragma unroll
        for (int j = 0; j < 8; j++)
            CPA(sbase + ABYTES + soff0 + j * 2048, pB0 + k0 + j * strideJ);
        CPCOMMIT();
    };

    issue(sb, 0);
    issue(sb + STAGE, 32);
    int cs = 0, is = 2;
    for (int c = 0; c < nch; c++) {
        if (c == nch - 1) { CPWAIT0(); } else { CPWAIT1(); }
        __syncthreads();
        if (c + 2 < nch) {
            issue(sb + is * STAGE, (c + 2) * 32);
            is = (is == 2) ? 0 : is + 1;
        }
        const uint32_t As = sb + cs * STAGE;
        const uint32_t Bs = As + ABYTES;
        #pragma unroll
        for (int kc = 0; kc < 4; kc++) {
            uint32_t afr[FM][4], bfr[8][2];
            #pragma unroll
            for (int fm = 0; fm < FM; fm++) {
                ldsm4(afr[fm],
                      As + fm * 2048 + aBase + ((((kc * 2) + cbA) ^ rmA) << 4));
                if (CVTA) {
                    #pragma unroll
                    for (int q = 0; q < 4; q++)
                        afr[fm][q] = to_tf32_u(afr[fm][q]);
                }
            }
            #pragma unroll
            for (int p = 0; p < 4; p++) {
                uint32_t t4[4];
                ldsm4(t4,
                      Bs + p * 2048 + bBase + ((((kc * 2) + cbB) ^ rmB) << 4));
                if (CVTB) {
                    #pragma unroll
                    for (int q = 0; q < 4; q++)
                        t4[q] = to_tf32_u(t4[q]);
                }
                bfr[2*p][0]   = t4[0]; bfr[2*p][1]   = t4[1];
                bfr[2*p+1][0] = t4[2]; bfr[2*p+1][1] = t4[3];
            }
            #pragma unroll
            for (int fm = 0; fm < FM; fm++)
                #pragma unroll
                for (int fn = 0; fn < 8; fn++)
                    mma_tf32(acc[fm][fn], afr[fm], bfr[fn]);
        }
        cs = (cs == 2) ? 0 : cs + 1;
    }
}

// ---------------------------------------------------------------------------
// Generic GEMM: D = A @ Bt^T (+ bias), optional TF32-rounded store.
// ---------------------------------------------------------------------------
template <int FM, int CVTA, int CVTB>
__global__ __launch_bounds__(128, GemmDims<FM>::OCC)
void mma_gemm(const float* __restrict__ A, const float* __restrict__ Bt,
              const float* __restrict__ bias, float* __restrict__ C,
              int M, int Nn, int K, int roundC)
{
    const int bm = blockIdx.y * (FM * 32);
    const int bn = blockIdx.x * 128;
    GEMM_PROLOG(FM);
    const float* pA0 = A  + (size_t)(bm + srow) * K + sc4 * 4;
    const float* pB0 = Bt + (size_t)(bn + srow) * K + sc4 * 4;
    const size_t strideJ = (size_t)16 * K;
    gemm_core<FM, CVTA, CVTB>(pA0, pB0, strideJ, K >> 5, sb, soff0,
                              aBase, rmA, cbA, bBase, rmB, cbB, acc);

    const int gid = lane >> 2, tig = lane & 3;
    #pragma unroll
    for (int fm = 0; fm < FM; fm++) {
        const int row = bm + wr * (FM * 16) + fm * 16 + gid;
        #pragma unroll
        for (int fn = 0; fn < 8; fn++) {
            const int col = bn + wc * 64 + fn * 8 + tig * 2;
            float b0 = 0.f, b1 = 0.f;
            if (bias != nullptr) { b0 = bias[col]; b1 = bias[col + 1]; }
            float2 v01, v23;
            v01.x = acc[fm][fn][0] + b0; v01.y = acc[fm][fn][1] + b1;
            v23.x = acc[fm][fn][2] + b0; v23.y = acc[fm][fn][3] + b1;
            if (roundC) {
                v01.x = to_tf32(v01.x); v01.y = to_tf32(v01.y);
                v23.x = to_tf32(v23.x); v23.y = to_tf32(v23.y);
            }
            *(float2*)(C + (size_t)row * Nn + col) = v01;
            *(float2*)(C + (size_t)(row + 8) * Nn + col) = v23;
        }
    }
}

// ---------------------------------------------------------------------------
// Split-K GEMM for skinny M=128: C += A @ Bt^T over K slice (atomics).
// ---------------------------------------------------------------------------
__global__ __launch_bounds__(128, 2)
void mma_gemm_splitk(const float* __restrict__ A, const float* __restrict__ Bt,
                     float* __restrict__ C, int M, int Nn, int K, int klen)
{
    const int bm = blockIdx.y * 128;
    const int bn = blockIdx.x * 128;
    const int kbase = blockIdx.z * klen;
    GEMM_PROLOG(4);
    const float* pA0 = A  + (size_t)(bm + srow) * K + kbase + sc4 * 4;
    const float* pB0 = Bt + (size_t)(bn + srow) * K + kbase + sc4 * 4;
    const size_t strideJ = (size_t)16 * K;
    gemm_core<4, 0, 0>(pA0, pB0, strideJ, klen >> 5, sb, soff0,
                       aBase, rmA, cbA, bBase, rmB, cbB, acc);

    const int gid = lane >> 2, tig = lane & 3;
    #pragma unroll
    for (int fm = 0; fm < 4; fm++) {
        const int row = bm + wr * 64 + fm * 16 + gid;
        #pragma unroll
        for (int fn = 0; fn < 8; fn++) {
            const int col = bn + wc * 64 + fn * 8 + tig * 2;
            atomicAdd(C + (size_t)row * Nn + col,       acc[fm][fn][0]);
            atomicAdd(C + (size_t)row * Nn + col + 1,   acc[fm][fn][1]);
            atomicAdd(C + (size_t)(row+8) * Nn + col,   acc[fm][fn][2]);
            atomicAdd(C + (size_t)(row+8) * Nn + col+1, acc[fm][fn][3]);
        }
    }
}

// ---------------------------------------------------------------------------
// Fused e_pre GEMM + scores epilogue (FM=2 tiles, 3 CTAs/SM).
// ---------------------------------------------------------------------------
__global__ __launch_bounds__(128, 3)
void epre_scores_gemm(const float* __restrict__ A, const float* __restrict__ Bt,
                      const float* __restrict__ sproj,
                      const float* __restrict__ cov,
                      const float* __restrict__ Wc,
                      const float* __restrict__ v,
                      float* __restrict__ scores)
{
    const int bm = blockIdx.y * 64;
    const int bn = blockIdx.x * 128;
    GEMM_PROLOG(2);
    const float* pA0 = A  + (size_t)(bm + srow) * H_ + sc4 * 4;
    const float* pB0 = Bt + (size_t)(bn + srow) * H_ + sc4 * 4;
    const size_t strideJ = (size_t)16 * H_;
    gemm_core<2, 0, 0>(pA0, pB0, strideJ, H_ >> 5, sb, soff0,
                       aBase, rmA, cbA, bBase, rmB, cbB, acc);

    const int gid = lane >> 2, tig = lane & 3;
    float vv[16], wcv[16];
    #pragma unroll
    for (int fn = 0; fn < 8; fn++) {
        const int col = bn + wc * 64 + fn * 8 + tig * 2;
        vv[2*fn]   = v[col];      vv[2*fn+1]  = v[col + 1];
        wcv[2*fn]  = Wc[col];     wcv[2*fn+1] = Wc[col + 1];
    }
    #pragma unroll
    for (int fm = 0; fm < 2; fm++) {
        const int r0 = bm + wr * 32 + fm * 16 + gid;
        const int r1 = r0 + 8;
        const int b0i = r0 / N_, b1i = r1 / N_;
        const float c0 = cov[r0], c1 = cov[r1];
        const float* sp0 = sproj + (size_t)b0i * A_;
        const float* sp1 = sproj + (size_t)b1i * A_;
        float p0 = 0.f, p1 = 0.f;
        #pragma unroll
        for (int fn = 0; fn < 8; fn++) {
            const int col = bn + wc * 64 + fn * 8 + tig * 2;
            p0 += vv[2*fn]   * tanh_approx(acc[fm][fn][0] + sp0[col]     + c0 * wcv[2*fn]);
            p0 += vv[2*fn+1] * tanh_approx(acc[fm][fn][1] + sp0[col + 1] + c0 * wcv[2*fn+1]);
            p1 += vv[2*fn]   * tanh_approx(acc[fm][fn][2] + sp1[col]     + c1 * wcv[2*fn]);
            p1 += vv[2*fn+1] * tanh_approx(acc[fm][fn][3] + sp1[col + 1] + c1 * wcv[2*fn+1]);
        }
        p0 += __shfl_xor_sync(0xffffffffu, p0, 1);
        p0 += __shfl_xor_sync(0xffffffffu, p0, 2);
        p1 += __shfl_xor_sync(0xffffffffu, p1, 1);
        p1 += __shfl_xor_sync(0xffffffffu, p1, 2);
        if (tig == 0) {
            atomicAdd(scores + r0, p0);
            atomicAdd(scores + r1, p1);
        }
    }
}

// ---------------------------------------------------------------------------
// Batched prologue: rounded transposes, zero-fills, s_t rounding, bias init.
// ---------------------------------------------------------------------------
#define PREP_T1 4096
#define PREP_T2 (PREP_T1 + 1024)
#define PREP_T3 (PREP_T2 + 1024)
#define PREP_ZS (PREP_T3 + 25)
#define PREP_ZP (PREP_ZS + 512)
#define PREP_RS (PREP_ZP + 128)
#define PREP_BI (PREP_RS + 4)
#define PREP_END PREP_BI

__device__ __forceinline__ void do_transpose32r(
    const float* __restrict__ in, float* __restrict__ out,
    int R, int C, int tx, int ty)
{
    __shared__ float t[32][33];
    const int c0 = tx * 32, r0 = ty * 32;
    const int x = threadIdx.x & 31, y = (threadIdx.x >> 5);
    #pragma unroll
    for (int j = 0; j < 32; j += 8)
        t[y + j][x] = in[(size_t)(r0 + y + j) * C + c0 + x];
    __syncthreads();
    #pragma unroll
    for (int j = 0; j < 32; j += 8)
        out[(size_t)(c0 + y + j) * R + r0 + x] = to_tf32(t[x][y + j]);
}

__global__ __launch_bounds__(256) void prep_kernel(
    const float* __restrict__ W_gs, float* __restrict__ WgsT,
    const float* __restrict__ W_h,  float* __restrict__ WhT,
    const float* __restrict__ W_s,  float* __restrict__ WsT,
    const float* __restrict__ s_t,  float* __restrict__ str,
    const float* __restrict__ b_gs, float* __restrict__ biascomb,
    float* __restrict__ scores, float* __restrict__ sproj)
{
    const int bid = blockIdx.x;
    if (bid < PREP_T1) {
        do_transpose32r(W_gs, WgsT, G_, H_, bid & 31, bid >> 5);
    } else if (bid < PREP_T2) {
        const int b = bid - PREP_T1;
        do_transpose32r(W_h, WhT, H_, A_, b & 31, b >> 5);
    } else if (bid < PREP_T3) {
        const int b = bid - PREP_T2;
        do_transpose32r(W_s, WsT, H_, A_, b & 31, b >> 5);
    } else if (bid < PREP_ZS) {
        const int i = (bid - PREP_T3) * 256 + threadIdx.x;
        if (i < BN_) scores[i] = 0.f;
    } else if (bid < PREP_ZP) {
        const int i = (bid - PREP_ZS) * 256 + threadIdx.x;
        sproj[i] = 0.f;
    } else if (bid < PREP_RS) {
        const int i = (bid - PREP_ZP) * 256 + threadIdx.x;
        float4 x = *(const float4*)(s_t + (size_t)i * 4);
        x.x = to_tf32(x.x); x.y = to_tf32(x.y);
        x.z = to_tf32(x.z); x.w = to_tf32(x.w);
        *(float4*)(str + (size_t)i * 4) = x;
    } else {
        const int h = (bid - PREP_RS) * 256 + threadIdx.x;
        biascomb[h] = b_gs[h];
    }
}

__global__ void bias_acc_kernel(const float* __restrict__ b_g,
                                const float* __restrict__ W_gs,
                                float* __restrict__ bias) {
    int h = blockIdx.x * blockDim.x + threadIdx.x;
    int k0 = blockIdx.y * 256;
    float acc = 0.f;
    #pragma unroll 4
    for (int k = k0; k < k0 + 256; k++)
        acc += b_g[k] * W_gs[(size_t)k * H_ + h];
    atomicAdd(&bias[h], acc);
}

// softmax over N=49 + context c[b,h] = sum_n alpha[n] * gstar[b,n,h]
__global__ __launch_bounds__(256) void context_kernel(
    const float* __restrict__ scores, const float* __restrict__ gstar,
    float* __restrict__ out)
{
    const int b = blockIdx.x;
    __shared__ float alpha[N_];
    const int tid = threadIdx.x;

    if (tid == 0) {
        float m = -1e30f;
        #pragma unroll
        for (int n = 0; n < N_; n++) m = fmaxf(m, scores[b * N_ + n]);
        float s = 0.f;
        #pragma unroll
        for (int n = 0; n < N_; n++) {
            float e = expf(scores[b * N_ + n] - m);
            alpha[n] = e;
            s += e;
        }
        float inv = 1.f / s;
        #pragma unroll
        for (int n = 0; n < N_; n++) alpha[n] *= inv;
    }
    __syncthreads();

    const float* gb = gstar + (size_t)b * N_ * H_;
    for (int h = tid; h < H_; h += 256) {
        float acc = 0.f;
        #pragma unroll
        for (int n = 0; n < N_; n++)
            acc += alpha[n] * gb[(size_t)n * H_ + h];
        out[(size_t)b * H_ + h] = acc;
    }
}

// ---------------------------------------------------------------------------
extern "C" void kernel_launch(void* const* d_in, const int* in_sizes, int n_in,
                              void* d_out, int out_size) {
    const float* X    = (const float*)d_in[0];   // [6272,4096]
    const float* s_t  = (const float*)d_in[1];   // [128,1024]
    const float* cov  = (const float*)d_in[2];   // [6272]
    const float* W_g  = (const float*)d_in[3];   // [4096,4096]
    const float* b_g  = (const float*)d_in[4];   // [4096]
    const float* W_gs = (const float*)d_in[5];   // [4096,1024]
    const float* b_gs = (const float*)d_in[6];   // [1024]
    const float* W_h  = (const float*)d_in[7];   // [1024,1024]
    const float* W_s  = (const float*)d_in[8];   // [1024,1024]
    const float* W_c  = (const float*)d_in[9];   // [1024]
    const float* v    = (const float*)d_in[10];  // [1024]
    float* out = (float*)d_out;                  // [128,1024]

    float *WcombT, *biascomb, *gstar, *WgsT, *WhT, *WsT;
    float *str, *sproj, *scores;
    cudaGetSymbolAddress((void**)&WcombT,   g_WcombT);
    cudaGetSymbolAddress((void**)&biascomb, g_biascomb);
    cudaGetSymbolAddress((void**)&gstar,    g_gstar);
    cudaGetSymbolAddress((void**)&WgsT,     g_WgsT);
    cudaGetSymbolAddress((void**)&WhT,      g_WhT);
    cudaGetSymbolAddress((void**)&WsT,      g_WsT);
    cudaGetSymbolAddress((void**)&str,      g_str);
    cudaGetSymbolAddress((void**)&sproj,    g_sproj);
    cudaGetSymbolAddress((void**)&scores,   g_scores);

    const int SM4 = GemmDims<4>::SMEM;   // 96KB
    const int SM2 = GemmDims<2>::SMEM;   // 72KB
    cudaFuncSetAttribute(mma_gemm<4, 0, 1>,
                         cudaFuncAttributeMaxDynamicSharedMemorySize, SM4);
    cudaFuncSetAttribute(mma_gemm<2, 1, 0>,
                         cudaFuncAttributeMaxDynamicSharedMemorySize, SM2);
    cudaFuncSetAttribute(mma_gemm_splitk,
                         cudaFuncAttributeMaxDynamicSharedMemorySize, SM4);
    cudaFuncSetAttribute(epre_scores_gemm,
                         cudaFuncAttributeMaxDynamicSharedMemorySize, SM2);

    // prologue: rounded transposes, zero-fills, s_t rounding, bias init
    prep_kernel<<<PREP_END, 256>>>(W_gs, WgsT, W_h, WhT, W_s, WsT,
                                   s_t, str, b_gs, biascomb, scores, sproj);
    bias_acc_kernel<<<dim3(H_ / 256, G_ / 256), 256>>>(b_g, W_gs, biascomb);

    // WcombT[h,g] = sum_k WgsT[h,k] * W_g[g,k]  (128x128 tiles, single wave)
    mma_gemm<4, 0, 1><<<dim3(G_ / 128, H_ / 128), 128, SM4>>>(
        WgsT, W_g, nullptr, WcombT, H_, G_, G_, 1);

    // g_star[m,h] = sum_k X[m,k] * WcombT[h,k] + bias  (64x128 tiles, 3/SM)
    mma_gemm<2, 1, 0><<<dim3(H_ / 128, BN_ / 64), 128, SM2>>>(
        X, WcombT, biascomb, gstar, BN_, H_, G_, 1);

    // s_proj[b,a] = sum_h str[b,h] * WsT[a,h]   (split-K x8, atomic)
    mma_gemm_splitk<<<dim3(A_ / 128, 1, 8), 128, SM4>>>(
        str, WsT, sproj, B_, A_, H_, H_ / 8);

    // fused: e_pre + tanh + v-dot -> scores  (64x128 tiles, 3/SM)
    epre_scores_gemm<<<dim3(A_ / 128, BN_ / 64), 128, SM2>>>(
        gstar, WhT, sproj, cov, W_c, v, scores);

    context_kernel<<<B_, 256>>>(scores, gstar, out);
}

// round 11
// speedup vs baseline: 1.0497x; 1.0150x over previous
#include <cuda_runtime.h>
#include <math.h>
#include <stdint.h>

// ===========================================================================
// img_attention via warp-level TF32 mma.sync (compute_103-safe)
//   c_img = softmax(v . tanh(Wh g* + Ws s + Wc cov)) @ g*
//   g*    = X @ (W_g @ W_gs) + (b_g @ W_gs + b_gs)      [algebraic fold]
// GEMMs: D[m,n] = sum_k A[m,k] * Bt[n,k]  (both K-major)
// R10: split-K partial-buffer GEMMs for Wcomb (x2) and gstar (x3) with
//      FM=4 tiles: low L2 traffic AND no wave-quantization tail.
// ===========================================================================

#define B_   128
#define N_   49
#define G_   4096
#define H_   1024
#define A_   1024
#define BN_  (B_ * N_)   // 6272

__device__ float g_WcombT[H_ * G_];       // [1024,4096] (rounded)
__device__ float g_biascomb[H_];
__device__ float g_gstar[BN_ * H_];       // [6272,1024] raw fp32
__device__ float g_parts[3 * BN_ * H_];   // split-K partial buffers (77MB)
__device__ float g_WgsT[H_ * G_];         // W_gs^T rounded [1024,4096]
__device__ float g_WhT[A_ * H_];          // rounded
__device__ float g_WsT[A_ * H_];          // rounded
__device__ float g_str[B_ * H_];          // s_t rounded
__device__ float g_sproj[B_ * A_];
__device__ float g_scores[BN_];

// ---------------------------------------------------------------------------
__device__ __forceinline__ uint32_t smem_u32(const void* p) {
    uint32_t a;
    asm("{ .reg .u64 t; cvta.to.shared.u64 t, %1; cvt.u32.u64 %0, t; }"
        : "=r"(a) : "l"(p));
    return a;
}
__device__ __forceinline__ float to_tf32(float x) {
    uint32_t u;
    asm("cvt.rna.tf32.f32 %0, %1;" : "=r"(u) : "f"(x));
    return __uint_as_float(u);
}
__device__ __forceinline__ uint32_t to_tf32_u(uint32_t x) {
    uint32_t u;
    asm("cvt.rna.tf32.f32 %0, %1;" : "=r"(u) : "f"(__uint_as_float(x)));
    return u;
}
__device__ __forceinline__ float tanh_approx(float x) {
    float y;
    asm("tanh.approx.f32 %0, %1;" : "=f"(y) : "f"(x));
    return y;
}
__device__ __forceinline__ void ldsm4(uint32_t* r, uint32_t addr) {
    asm volatile("ldmatrix.sync.aligned.m8n8.x4.shared.b16 {%0,%1,%2,%3}, [%4];"
                 : "=r"(r[0]), "=r"(r[1]), "=r"(r[2]), "=r"(r[3]) : "r"(addr));
}
__device__ __forceinline__ void mma_tf32(float* d, const uint32_t* a,
                                         const uint32_t* b) {
    asm volatile(
        "mma.sync.aligned.m16n8k8.row.col.f32.tf32.tf32.f32 "
        "{%0,%1,%2,%3}, {%4,%5,%6,%7}, {%8,%9}, {%0,%1,%2,%3};"
        : "+f"(d[0]), "+f"(d[1]), "+f"(d[2]), "+f"(d[3])
        : "r"(a[0]), "r"(a[1]), "r"(a[2]), "r"(a[3]), "r"(b[0]), "r"(b[1]));
}
#define CPA(dst, src) \
    asm volatile("cp.async.cg.shared.global [%0], [%1], 16;" \
                 :: "r"(dst), "l"(src) : "memory")
#define CPCOMMIT() asm volatile("cp.async.commit_group;" ::: "memory")
#define CPWAIT1()  asm volatile("cp.async.wait_group 1;" ::: "memory")
#define CPWAIT0()  asm volatile("cp.async.wait_group 0;" ::: "memory")

// ---------------------------------------------------------------------------
// Templated GEMM core. FM = A-fragments per warp (M-tile = FM*32).
//   FM=4: block 128x128, 2 CTAs/SM (96KB smem)
//   FM=2: block  64x128, 3 CTAs/SM (72KB smem)
// 2x2 warps; warp tile (FM*16)x64. BK=32. 3-stage cp.async ring.
// ---------------------------------------------------------------------------
template <int FM>
struct GemmDims {
    static const int ABYTES = FM * 32 * 128;
    static const int STAGE  = ABYTES + 16384;
    static const int SMEM   = 3 * STAGE;
    static const int OCC    = (FM == 2) ? 3 : 2;
};

#define GEMM_PROLOG(FM)                                                       \
    extern __shared__ char smem[];                                            \
    const uint32_t sb = smem_u32(smem);                                       \
    const int tid = threadIdx.x;                                              \
    const int lane = tid & 31;                                                \
    const int wid = tid >> 5;                                                 \
    const int wr = wid >> 1;   /* 0..1 */                                     \
    const int wc = wid & 1;    /* 0..1 */                                     \
    const int srow = tid >> 3, sc4 = tid & 7;                                 \
    const uint32_t soff0 = (uint32_t)srow * 128 + ((sc4 ^ (srow & 7)) << 4);  \
    const int aRow = wr * (FM * 16) + ((lane >> 3) & 1) * 8 + (lane & 7);     \
    const int cbA = lane >> 4;                                                \
    const uint32_t aBase = (uint32_t)aRow * 128;                              \
    const int rmA = aRow & 7;                                                 \
    const int bRow = wc * 64 + (lane >> 4) * 8 + (lane & 7);                  \
    const int cbB = (lane >> 3) & 1;                                          \
    const uint32_t bBase = (uint32_t)bRow * 128;                              \
    const int rmB = bRow & 7;                                                 \
    float acc[FM][8][4];                                                      \
    _Pragma("unroll") for (int i = 0; i < FM; i++)                            \
        _Pragma("unroll") for (int j = 0; j < 8; j++)                         \
            _Pragma("unroll") for (int q = 0; q < 4; q++) acc[i][j][q] = 0.f;

template <int FM, int CVTA, int CVTB>
__device__ __forceinline__ void gemm_core(
    const float* __restrict__ pA0, const float* __restrict__ pB0,
    size_t strideJ, int nch, uint32_t sb, uint32_t soff0,
    uint32_t aBase, int rmA, int cbA,
    uint32_t bBase, int rmB, int cbB,
    float (&acc)[FM][8][4])
{
    const int ABYTES = GemmDims<FM>::ABYTES;
    const int STAGE  = GemmDims<FM>::STAGE;
    const int JA = FM * 2;

    auto issue = [&](uint32_t sbase, int k0) {
        #pragma unroll
        for (int j = 0; j < JA; j++)
            CPA(sbase + soff0 + j * 2048, pA0 + k0 + j * strideJ);
        #pragma unroll
        for (int j = 0; j < 8; j++)
            CPA(sbase + ABYTES + soff0 + j * 2048, pB0 + k0 + j * strideJ);
        CPCOMMIT();
    };

    issue(sb, 0);
    issue(sb + STAGE, 32);
    int cs = 0, is = 2;
    for (int c = 0; c < nch; c++) {
        if (c == nch - 1) { CPWAIT0(); } else { CPWAIT1(); }
        __syncthreads();
        if (c + 2 < nch) {
            issue(sb + is * STAGE, (c + 2) * 32);
            is = (is == 2) ? 0 : is + 1;
        }
        const uint32_t As = sb + cs * STAGE;
        const uint32_t Bs = As + ABYTES;
        #pragma unroll
        for (int kc = 0; kc < 4; kc++) {
            uint32_t afr[FM][4], bfr[8][2];
            #pragma unroll
            for (int fm = 0; fm < FM; fm++) {
                ldsm4(afr[fm],
                      As + fm * 2048 + aBase + ((((kc * 2) + cbA) ^ rmA) << 4));
                if (CVTA) {
                    #pragma unroll
                    for (int q = 0; q < 4; q++)
                        afr[fm][q] = to_tf32_u(afr[fm][q]);
                }
            }
            #pragma unroll
            for (int p = 0; p < 4; p++) {
                uint32_t t4[4];
                ldsm4(t4,
                      Bs + p * 2048 + bBase + ((((kc * 2) + cbB) ^ rmB) << 4));
                if (CVTB) {
                    #pragma unroll
                    for (int q = 0; q < 4; q++)
                        t4[q] = to_tf32_u(t4[q]);
                }
                bfr[2*p][0]   = t4[0]; bfr[2*p][1]   = t4[1];
                bfr[2*p+1][0] = t4[2]; bfr[2*p+1][1] = t4[3];
            }
            #pragma unroll
            for (int fm = 0; fm < FM; fm++)
                #pragma unroll
                for (int fn = 0; fn < 8; fn++)
                    mma_tf32(acc[fm][fn], afr[fm], bfr[fn]);
        }
        cs = (cs == 2) ? 0 : cs + 1;
    }
}

// ---------------------------------------------------------------------------
// Split-K partial GEMM: Cpart[z] = A @ Bt^T over K slice z.
// grid.z = #splits; slice z covers chunks [z*nchA, min((z+1)*nchA, K/32)).
// Plain stores into per-z partial buffer (no atomics).
// ---------------------------------------------------------------------------
template <int FM, int CVTA, int CVTB>
__global__ __launch_bounds__(128, GemmDims<FM>::OCC)
void mma_gemm_part(const float* __restrict__ A, const float* __restrict__ Bt,
                   float* __restrict__ Cparts, size_t zstride,
                   int Nn, int K, int nchA)
{
    const int bm = blockIdx.y * (FM * 32);
    const int bn = blockIdx.x * 128;
    const int z  = blockIdx.z;
    const int kbase = z * nchA * 32;
    int nch = (K >> 5) - z * nchA;
    if (nch > nchA) nch = nchA;
    float* C = Cparts + (size_t)z * zstride;

    GEMM_PROLOG(FM);
    const float* pA0 = A  + (size_t)(bm + srow) * K + kbase + sc4 * 4;
    const float* pB0 = Bt + (size_t)(bn + srow) * K + kbase + sc4 * 4;
    const size_t strideJ = (size_t)16 * K;
    gemm_core<FM, CVTA, CVTB>(pA0, pB0, strideJ, nch, sb, soff0,
                              aBase, rmA, cbA, bBase, rmB, cbB, acc);

    const int gid = lane >> 2, tig = lane & 3;
    #pragma unroll
    for (int fm = 0; fm < FM; fm++) {
        const int row = bm + wr * (FM * 16) + fm * 16 + gid;
        #pragma unroll
        for (int fn = 0; fn < 8; fn++) {
            const int col = bn + wc * 64 + fn * 8 + tig * 2;
            float2 v01, v23;
            v01.x = acc[fm][fn][0]; v01.y = acc[fm][fn][1];
            v23.x = acc[fm][fn][2]; v23.y = acc[fm][fn][3];
            *(float2*)(C + (size_t)row * Nn + col) = v01;
            *(float2*)(C + (size_t)(row + 8) * Nn + col) = v23;
        }
    }
}

// ---------------------------------------------------------------------------
// Split-K GEMM for skinny M=128 (sproj): C += A @ Bt^T over K slice, atomics.
// ---------------------------------------------------------------------------
__global__ __launch_bounds__(128, 2)
void mma_gemm_splitk(const float* __restrict__ A, const float* __restrict__ Bt,
                     float* __restrict__ C, int M, int Nn, int K, int klen)
{
    const int bm = blockIdx.y * 128;
    const int bn = blockIdx.x * 128;
    const int kbase = blockIdx.z * klen;
    GEMM_PROLOG(4);
    const float* pA0 = A  + (size_t)(bm + srow) * K + kbase + sc4 * 4;
    const float* pB0 = Bt + (size_t)(bn + srow) * K + kbase + sc4 * 4;
    const size_t strideJ = (size_t)16 * K;
    gemm_core<4, 0, 0>(pA0, pB0, strideJ, klen >> 5, sb, soff0,
                       aBase, rmA, cbA, bBase, rmB, cbB, acc);

    const int gid = lane >> 2, tig = lane & 3;
    #pragma unroll
    for (int fm = 0; fm < 4; fm++) {
        const int row = bm + wr * 64 + fm * 16 + gid;
        #pragma unroll
        for (int fn = 0; fn < 8; fn++) {
            const int col = bn + wc * 64 + fn * 8 + tig * 2;
            atomicAdd(C + (size_t)row * Nn + col,       acc[fm][fn][0]);
            atomicAdd(C + (size_t)row * Nn + col + 1,   acc[fm][fn][1]);
            atomicAdd(C + (size_t)(row+8) * Nn + col,   acc[fm][fn][2]);
            atomicAdd(C + (size_t)(row+8) * Nn + col+1, acc[fm][fn][3]);
        }
    }
}

// ---------------------------------------------------------------------------
// Fused e_pre GEMM + scores epilogue (FM=2 tiles, 3 CTAs/SM).
// A = gstar (raw fp32 -> CVTA=1), B = WhT (pre-rounded).
// ---------------------------------------------------------------------------
__global__ __launch_bounds__(128, 3)
void epre_scores_gemm(const float* __restrict__ A, const float* __restrict__ Bt,
                      const float* __restrict__ sproj,
                      const float* __restrict__ cov,
                      const float* __restrict__ Wc,
                      const float* __restrict__ v,
                      float* __restrict__ scores)
{
    const int bm = blockIdx.y * 64;
    const int bn = blockIdx.x * 128;
    GEMM_PROLOG(2);
    const float* pA0 = A  + (size_t)(bm + srow) * H_ + sc4 * 4;
    const float* pB0 = Bt + (size_t)(bn + srow) * H_ + sc4 * 4;
    const size_t strideJ = (size_t)16 * H_;
    gemm_core<2, 1, 0>(pA0, pB0, strideJ, H_ >> 5, sb, soff0,
                       aBase, rmA, cbA, bBase, rmB, cbB, acc);

    const int gid = lane >> 2, tig = lane & 3;
    float vv[16], wcv[16];
    #pragma unroll
    for (int fn = 0; fn < 8; fn++) {
        const int col = bn + wc * 64 + fn * 8 + tig * 2;
        vv[2*fn]   = v[col];      vv[2*fn+1]  = v[col + 1];
        wcv[2*fn]  = Wc[col];     wcv[2*fn+1] = Wc[col + 1];
    }
    #pragma unroll
    for (int fm = 0; fm < 2; fm++) {
        const int r0 = bm + wr * 32 + fm * 16 + gid;
        const int r1 = r0 + 8;
        const int b0i = r0 / N_, b1i = r1 / N_;
        const float c0 = cov[r0], c1 = cov[r1];
        const float* sp0 = sproj + (size_t)b0i * A_;
        const float* sp1 = sproj + (size_t)b1i * A_;
        float p0 = 0.f, p1 = 0.f;
        #pragma unroll
        for (int fn = 0; fn < 8; fn++) {
            const int col = bn + wc * 64 + fn * 8 + tig * 2;
            p0 += vv[2*fn]   * tanh_approx(acc[fm][fn][0] + sp0[col]     + c0 * wcv[2*fn]);
            p0 += vv[2*fn+1] * tanh_approx(acc[fm][fn][1] + sp0[col + 1] + c0 * wcv[2*fn+1]);
            p1 += vv[2*fn]   * tanh_approx(acc[fm][fn][2] + sp1[col]     + c1 * wcv[2*fn]);
            p1 += vv[2*fn+1] * tanh_approx(acc[fm][fn][3] + sp1[col + 1] + c1 * wcv[2*fn+1]);
        }
        p0 += __shfl_xor_sync(0xffffffffu, p0, 1);
        p0 += __shfl_xor_sync(0xffffffffu, p0, 2);
        p1 += __shfl_xor_sync(0xffffffffu, p1, 1);
        p1 += __shfl_xor_sync(0xffffffffu, p1, 2);
        if (tig == 0) {
            atomicAdd(scores + r0, p0);
            atomicAdd(scores + r1, p1);
        }
    }
}

// ---------------------------------------------------------------------------
// Reductions over split-K partials.
// ---------------------------------------------------------------------------
// WcombT = tf32(p0 + p1)  (4.19M floats, float4)
__global__ __launch_bounds__(256) void reduce2_round_kernel(
    const float* __restrict__ p0, const float* __restrict__ p1,
    float* __restrict__ out)
{
    const size_t i = ((size_t)blockIdx.x * 256 + threadIdx.x) * 4;
    float4 a = *(const float4*)(p0 + i);
    float4 b = *(const float4*)(p1 + i);
    float4 r;
    r.x = to_tf32(a.x + b.x); r.y = to_tf32(a.y + b.y);
    r.z = to_tf32(a.z + b.z); r.w = to_tf32(a.w + b.w);
    *(float4*)(out + i) = r;
}

// gstar = p0 + p1 + p2 + biascomb[col]  (25.7M floats, float4)
__global__ __launch_bounds__(256) void reduce3_bias_kernel(
    const float* __restrict__ p0, const float* __restrict__ p1,
    const float* __restrict__ p2, const float* __restrict__ bias,
    float* __restrict__ out)
{
    const size_t idx = (size_t)blockIdx.x * 256 + threadIdx.x;  // float4 index
    const size_t i = idx * 4;
    const int col = (int)(i & (H_ - 1));
    float4 a = *(const float4*)(p0 + i);
    float4 b = *(const float4*)(p1 + i);
    float4 c = *(const float4*)(p2 + i);
    float4 d = *(const float4*)(bias + col);
    float4 r;
    r.x = a.x + b.x + c.x + d.x;
    r.y = a.y + b.y + c.y + d.y;
    r.z = a.z + b.z + c.z + d.z;
    r.w = a.w + b.w + c.w + d.w;
    *(float4*)(out + i) = r;
}

// ---------------------------------------------------------------------------
// Batched prologue: rounded transposes, zero-fills, s_t rounding, bias init.
// ---------------------------------------------------------------------------
#define PREP_T1 4096
#define PREP_T2 (PREP_T1 + 1024)
#define PREP_T3 (PREP_T2 + 1024)
#define PREP_ZS (PREP_T3 + 25)
#define PREP_ZP (PREP_ZS + 512)
#define PREP_RS (PREP_ZP + 128)
#define PREP_BI (PREP_RS + 4)
#define PREP_END PREP_BI

__device__ __forceinline__ void do_transpose32r(
    const float* __restrict__ in, float* __restrict__ out,
    int R, int C, int tx, int ty)
{
    __shared__ float t[32][33];
    const int c0 = tx * 32, r0 = ty * 32;
    const int x = threadIdx.x & 31, y = (threadIdx.x >> 5);
    #pragma unroll
    for (int j = 0; j < 32; j += 8)
        t[y + j][x] = in[(size_t)(r0 + y + j) * C + c0 + x];
    __syncthreads();
    #pragma unroll
    for (int j = 0; j < 32; j += 8)
        out[(size_t)(c0 + y + j) * R + r0 + x] = to_tf32(t[x][y + j]);
}

__global__ __launch_bounds__(256) void prep_kernel(
    const float* __restrict__ W_gs, float* __restrict__ WgsT,
    const float* __restrict__ W_h,  float* __restrict__ WhT,
    const float* __restrict__ W_s,  float* __restrict__ WsT,
    const float* __restrict__ s_t,  float* __restrict__ str,
    const float* __restrict__ b_gs, float* __restrict__ biascomb,
    float* __restrict__ scores, float* __restrict__ sproj)
{
    const int bid = blockIdx.x;
    if (bid < PREP_T1) {
        do_transpose32r(W_gs, WgsT, G_, H_, bid & 31, bid >> 5);
    } else if (bid < PREP_T2) {
        const int b = bid - PREP_T1;
        do_transpose32r(W_h, WhT, H_, A_, b & 31, b >> 5);
    } else if (bid < PREP_T3) {
        const int b = bid - PREP_T2;
        do_transpose32r(W_s, WsT, H_, A_, b & 31, b >> 5);
    } else if (bid < PREP_ZS) {
        const int i = (bid - PREP_T3) * 256 + threadIdx.x;
        if (i < BN_) scores[i] = 0.f;
    } else if (bid < PREP_ZP) {
        const int i = (bid - PREP_ZS) * 256 + threadIdx.x;
        sproj[i] = 0.f;
    } else if (bid < PREP_RS) {
        const int i = (bid - PREP_ZP) * 256 + threadIdx.x;
        float4 x = *(const float4*)(s_t + (size_t)i * 4);
        x.x = to_tf32(x.x); x.y = to_tf32(x.y);
        x.z = to_tf32(x.z); x.w = to_tf32(x.w);
        *(float4*)(str + (size_t)i * 4) = x;
    } else {
        const int h = (bid - PREP_RS) * 256 + threadIdx.x;
        biascomb[h] = b_gs[h];
    }
}

__global__ void bias_acc_kernel(const float* __restrict__ b_g,
                                const float* __restrict__ W_gs,
                                float* __restrict__ bias) {
    int h = blockIdx.x * blockDim.x + threadIdx.x;
    int k0 = blockIdx.y * 256;
    float acc = 0.f;
    #pragma unroll 4
    for (int k = k0; k < k0 + 256; k++)
        acc += b_g[k] * W_gs[(size_t)k * H_ + h];
    atomicAdd(&bias[h], acc);
}

// softmax over N=49 + context c[b,h] = sum_n alpha[n] * gstar[b,n,h]
__global__ __launch_bounds__(256) void context_kernel(
    const float* __restrict__ scores, const float* __restrict__ gstar,
    float* __restrict__ out)
{
    const int b = blockIdx.x;
    __shared__ float alpha[N_];
    const int tid = threadIdx.x;

    if (tid == 0) {
        float m = -1e30f;
        #pragma unroll
        for (int n = 0; n < N_; n++) m = fmaxf(m, scores[b * N_ + n]);
        float s = 0.f;
        #pragma unroll
        for (int n = 0; n < N_; n++) {
            float e = expf(scores[b * N_ + n] - m);
            alpha[n] = e;
            s += e;
        }
        float inv = 1.f / s;
        #pragma unroll
        for (int n = 0; n < N_; n++) alpha[n] *= inv;
    }
    __syncthreads();

    const float* gb = gstar + (size_t)b * N_ * H_;
    for (int h = tid; h < H_; h += 256) {
        float acc = 0.f;
        #pragma unroll
        for (int n = 0; n < N_; n++)
            acc += alpha[n] * gb[(size_t)n * H_ + h];
        out[(size_t)b * H_ + h] = acc;
    }
}

// ---------------------------------------------------------------------------
extern "C" void kernel_launch(void* const* d_in, const int* in_sizes, int n_in,
                              void* d_out, int out_size) {
    const float* X    = (const float*)d_in[0];   // [6272,4096]
    const float* s_t  = (const float*)d_in[1];   // [128,1024]
    const float* cov  = (const float*)d_in[2];   // [6272]
    const float* W_g  = (const float*)d_in[3];   // [4096,4096]
    const float* b_g  = (const float*)d_in[4];   // [4096]
    const float* W_gs = (const float*)d_in[5];   // [4096,1024]
    const float* b_gs = (const float*)d_in[6];   // [1024]
    const float* W_h  = (const float*)d_in[7];   // [1024,1024]
    const float* W_s  = (const float*)d_in[8];   // [1024,1024]
    const float* W_c  = (const float*)d_in[9];   // [1024]
    const float* v    = (const float*)d_in[10];  // [1024]
    float* out = (float*)d_out;                  // [128,1024]

    float *WcombT, *biascomb, *gstar, *parts, *WgsT, *WhT, *WsT;
    float *str, *sproj, *scores;
    cudaGetSymbolAddress((void**)&WcombT,   g_WcombT);
    cudaGetSymbolAddress((void**)&biascomb, g_biascomb);
    cudaGetSymbolAddress((void**)&gstar,    g_gstar);
    cudaGetSymbolAddress((void**)&parts,    g_parts);
    cudaGetSymbolAddress((void**)&WgsT,     g_WgsT);
    cudaGetSymbolAddress((void**)&WhT,      g_WhT);
    cudaGetSymbolAddress((void**)&WsT,      g_WsT);
    cudaGetSymbolAddress((void**)&str,      g_str);
    cudaGetSymbolAddress((void**)&sproj,    g_sproj);
    cudaGetSymbolAddress((void**)&scores,   g_scores);

    const int SM4 = GemmDims<4>::SMEM;   // 96KB
    const int SM2 = GemmDims<2>::SMEM;   // 72KB
    cudaFuncSetAttribute(mma_gemm_part<4, 0, 1>,
                         cudaFuncAttributeMaxDynamicSharedMemorySize, SM4);
    cudaFuncSetAttribute(mma_gemm_part<4, 1, 0>,
                         cudaFuncAttributeMaxDynamicSharedMemorySize, SM4);
    cudaFuncSetAttribute(mma_gemm_splitk,
                         cudaFuncAttributeMaxDynamicSharedMemorySize, SM4);
    cudaFuncSetAttribute(epre_scores_gemm,
                         cudaFuncAttributeMaxDynamicSharedMemorySize, SM2);

    // prologue: rounded transposes, zero-fills, s_t rounding, bias init
    prep_kernel<<<PREP_END, 256>>>(W_gs, WgsT, W_h, WhT, W_s, WsT,
                                   s_t, str, b_gs, biascomb, scores, sproj);
    bias_acc_kernel<<<dim3(H_ / 256, G_ / 256), 256>>>(b_g, W_gs, biascomb);

    // WcombT = WgsT @ W_g^T, split-K x2 (64+64 chunks), reduce+round
    mma_gemm_part<4, 0, 1><<<dim3(G_ / 128, H_ / 128, 2), 128, SM4>>>(
        WgsT, W_g, parts, (size_t)H_ * G_, G_, G_, 64);
    reduce2_round_kernel<<<(H_ * G_ / 4) / 256, 256>>>(
        parts, parts + (size_t)H_ * G_, WcombT);

    // gstar partials = X @ WcombT^T, split-K x3 (43/43/42 chunks)
    mma_gemm_part<4, 1, 0><<<dim3(H_ / 128, BN_ / 128, 3), 128, SM4>>>(
        X, WcombT, parts, (size_t)BN_ * H_, H_, G_, 43);
    // gstar = p0+p1+p2 + biascomb
    reduce3_bias_kernel<<<(BN_ * H_ / 4) / 256, 256>>>(
        parts, parts + (size_t)BN_ * H_, parts + 2 * (size_t)BN_ * H_,
        biascomb, gstar);

    // s_proj = str @ WsT^T   (split-K x8, atomic)
    mma_gemm_splitk<<<dim3(A_ / 128, 1, 8), 128, SM4>>>(
        str, WsT, sproj, B_, A_, H_, H_ / 8);

    // fused: e_pre + tanh + v-dot -> scores
    epre_scores_gemm<<<dim3(A_ / 128, BN_ / 64), 128, SM2>>>(
        gstar, WhT, sproj, cov, W_c, v, scores);

    context_kernel<<<B_, 256>>>(scores, gstar, out);
}